// round 1
// baseline (speedup 1.0000x reference)
#include <cuda_runtime.h>

#define NQ      12
#define DIM     4096        // 2^12 amplitudes
#define NT      256         // threads per CTA
#define NLAYERS 4

__device__ __forceinline__ void apply1q(float2* psi, int q,
                                        float2 u00, float2 u01,
                                        float2 u10, float2 u11, int t)
{
    const int bpos = NQ - 1 - q;          // bit position (wire 0 = MSB)
    const int s    = 1 << bpos;           // pair stride
#pragma unroll 4
    for (int k = t; k < DIM / 2; k += NT) {
        int i0 = ((k >> bpos) << (bpos + 1)) | (k & (s - 1));
        int i1 = i0 + s;
        float2 a0 = psi[i0];
        float2 a1 = psi[i1];
        float2 n0, n1;
        n0.x = u00.x * a0.x - u00.y * a0.y + u01.x * a1.x - u01.y * a1.y;
        n0.y = u00.x * a0.y + u00.y * a0.x + u01.x * a1.y + u01.y * a1.x;
        n1.x = u10.x * a0.x - u10.y * a0.y + u11.x * a1.x - u11.y * a1.y;
        n1.y = u10.x * a0.y + u10.y * a0.x + u11.x * a1.y + u11.y * a1.x;
        psi[i0] = n0;
        psi[i1] = n1;
    }
}

__global__ void __launch_bounds__(NT)
qsim_kernel(const float* __restrict__ x,       // (B, 12)
            const float* __restrict__ w,       // (4, 12, 3)
            const float* __restrict__ ent,     // (4, 12)
            float* __restrict__ out)           // (B, 12)
{
    __shared__ float2 psi[DIM];                        // 32 KB statevector
    __shared__ float  red[(NT / 32) * NQ];             // reduction scratch

    const int b = blockIdx.x;
    const int t = threadIdx.x;

    // |0...0>
    for (int i = t; i < DIM; i += NT) psi[i] = make_float2(0.f, 0.f);
    if (t == 0) psi[0] = make_float2(1.f, 0.f);
    __syncthreads();

    const float PI = 3.14159265358979323846f;

    // ---- encoding: fused U = RZ(x^2*pi) @ RY(x*pi) per qubit (per-sample) ----
    for (int q = 0; q < NQ; q++) {
        float xv = __ldg(&x[b * NQ + q]);
        float c, s;
        sincosf(0.5f * PI * xv, &s, &c);               // RY(x*pi): cos/sin of t/2
        float ch, sh;
        sincosf(0.5f * PI * xv * xv, &sh, &ch);        // RZ(x^2*pi) phase a/2
        // e^{-ia/2} = (ch, -sh);  e^{+ia/2} = (ch, +sh)
        // U00 = e^{-ia/2} c ; U01 = -e^{-ia/2} s ; U10 = e^{+ia/2} s ; U11 = e^{+ia/2} c
        float2 u00 = make_float2( c * ch, -c * sh);
        float2 u01 = make_float2(-s * ch,  s * sh);
        float2 u10 = make_float2( s * ch,  s * sh);
        float2 u11 = make_float2( c * ch,  c * sh);
        apply1q(psi, q, u00, u01, u10, u11, t);
        __syncthreads();
    }

    // ---- variational layers ----
    for (int l = 0; l < NLAYERS; l++) {
        // Rot(phi, theta, omega) = RZ(om) @ RY(th) @ RZ(phi)  (shared across batch)
        for (int q = 0; q < NQ; q++) {
            float phi = __ldg(&w[(l * NQ + q) * 3 + 0]);
            float th  = __ldg(&w[(l * NQ + q) * 3 + 1]);
            float om  = __ldg(&w[(l * NQ + q) * 3 + 2]);
            float c, s;
            sincosf(0.5f * th, &s, &c);
            float ap = 0.5f * (om + phi);
            float am = 0.5f * (om - phi);
            float cp, sp, cm, sm;
            sincosf(ap, &sp, &cp);
            sincosf(am, &sm, &cm);
            // U00 = e^{-i*ap} c ; U01 = -e^{-i*am} s ; U10 = e^{+i*am} s ; U11 = e^{+i*ap} c
            float2 u00 = make_float2( c * cp, -c * sp);
            float2 u01 = make_float2(-s * cm,  s * sm);
            float2 u10 = make_float2( s * cm,  s * sm);
            float2 u11 = make_float2( c * cp,  c * sp);
            apply1q(psi, q, u00, u01, u10, u11, t);
            __syncthreads();
        }
        // conditional CNOT ring
        for (int q = 0; q < NQ; q++) {
            if (__ldg(&ent[l * NQ + q]) > 0.5f) {
                const int cb = NQ - 1 - q;                 // control bit pos
                const int tb = NQ - 1 - ((q + 1) % NQ);    // target bit pos
                const int lo = cb < tb ? cb : tb;
                const int hi = cb < tb ? tb : cb;
#pragma unroll 4
                for (int k = t; k < DIM / 4; k += NT) {
                    int i = ((k >> lo) << (lo + 1)) | (k & ((1 << lo) - 1));
                    i = ((i >> hi) << (hi + 1)) | (i & ((1 << hi) - 1));
                    i |= (1 << cb);                        // control = 1
                    int j = i | (1 << tb);                 // target 0 <-> 1
                    float2 tmp = psi[i];
                    psi[i] = psi[j];
                    psi[j] = tmp;
                }
                __syncthreads();
            }
        }
    }

    // ---- readout: <Z_q> = sum_s p(s) * (1 - 2*bit_q(s)) ----
    float acc[NQ];
#pragma unroll
    for (int q = 0; q < NQ; q++) acc[q] = 0.f;

    for (int i = t; i < DIM; i += NT) {
        float2 a = psi[i];
        float p = a.x * a.x + a.y * a.y;
#pragma unroll
        for (int q = 0; q < NQ; q++)
            acc[q] += ((i >> (NQ - 1 - q)) & 1) ? -p : p;
    }

    const int wid  = t >> 5;
    const int lane = t & 31;
#pragma unroll
    for (int q = 0; q < NQ; q++) {
        float v = acc[q];
#pragma unroll
        for (int o = 16; o; o >>= 1) v += __shfl_xor_sync(0xFFFFFFFFu, v, o);
        if (lane == 0) red[wid * NQ + q] = v;
    }
    __syncthreads();

    if (t < NQ) {
        float ssum = 0.f;
#pragma unroll
        for (int wi = 0; wi < NT / 32; wi++) ssum += red[wi * NQ + t];
        out[b * NQ + t] = ssum;   // SCALE = 1
    }
}

extern "C" void kernel_launch(void* const* d_in, const int* in_sizes, int n_in,
                              void* d_out, int out_size)
{
    const float* x   = (const float*)d_in[0];   // (B, 12)
    const float* w   = (const float*)d_in[1];   // (4, 12, 3)
    const float* ent = (const float*)d_in[2];   // (4, 12)
    float* out = (float*)d_out;                 // (B, 12)

    int B = in_sizes[0] / NQ;
    qsim_kernel<<<B, NT>>>(x, w, ent, out);
}

// round 2
// speedup vs baseline: 1.9461x; 1.9461x over previous
#include <cuda_runtime.h>

#define NQ      12
#define DIM     4096
#define NT      256
#define NLAYERS 4
#define NGATES  60          // 12 encoding + 48 Rot

typedef unsigned long long u64;

// ---- packed f32x2 helpers (re in lo 32 bits, im in hi 32 bits) ----
__device__ __forceinline__ u64 pack2(float lo, float hi) {
    u64 r; asm("mov.b64 %0, {%1, %2};" : "=l"(r) : "f"(lo), "f"(hi)); return r;
}
__device__ __forceinline__ void unpack2(u64 v, float& lo, float& hi) {
    asm("mov.b64 {%0, %1}, %2;" : "=f"(lo), "=f"(hi) : "l"(v));
}
__device__ __forceinline__ u64 swap2(u64 v) {
    u64 r;
    asm("{\n\t.reg .b32 l, h;\n\tmov.b64 {l, h}, %1;\n\tmov.b64 %0, {h, l};\n\t}"
        : "=l"(r) : "l"(v));
    return r;
}
__device__ __forceinline__ u64 ffma2(u64 a, u64 b, u64 c) {
    u64 r; asm("fma.rn.f32x2 %0, %1, %2, %3;" : "=l"(r) : "l"(a), "l"(b), "l"(c)); return r;
}
__device__ __forceinline__ u64 fmul2(u64 a, u64 b) {
    u64 r; asm("mul.rn.f32x2 %0, %1, %2;" : "=l"(r) : "l"(a), "l"(b)); return r;
}

// Gate coefficient layout per gate in smem (8 u64):
//   [0]=A(u00) [1]=B(u00) [2]=A(u01) [3]=B(u01) [4]=A(u10) [5]=B(u10) [6]=A(u11) [7]=B(u11)
// where A(c)=(c.re,c.re), B(c)=(-c.im,c.im): complex mul c*m = A(c)*m + B(c)*swap(m).

// ---- gate on a register bit P (wires 8..11): pure register FMA ----
template<int P>
__device__ __forceinline__ void gate_reg(u64* st, const u64* g) {
    u64 A00=g[0],B00=g[1],A01=g[2],B01=g[3],A10=g[4],B10=g[5],A11=g[6],B11=g[7];
#pragma unroll
    for (int k = 0; k < 8; k++) {
        const int r0 = ((k >> P) << (P + 1)) | (k & ((1 << P) - 1));
        const int r1 = r0 | (1 << P);
        u64 m0 = st[r0], m1 = st[r1];
        u64 s0 = swap2(m0), s1 = swap2(m1);
        u64 n0 = ffma2(A01, m1, ffma2(B01, s1, ffma2(B00, s0, fmul2(A00, m0))));
        u64 n1 = ffma2(A11, m1, ffma2(B11, s1, ffma2(B10, s0, fmul2(A10, m0))));
        st[r0] = n0; st[r1] = n1;
    }
}

// ---- gate on a lane bit LB (wires 3..7): shuffle exchange ----
template<int LB>
__device__ __forceinline__ void gate_lane(u64* st, const u64* g, int lane) {
    const int bit = (lane >> LB) & 1;
    u64 cAm = bit ? g[6] : g[0];
    u64 cBm = bit ? g[7] : g[1];
    u64 cAo = bit ? g[4] : g[2];
    u64 cBo = bit ? g[5] : g[3];
#pragma unroll
    for (int r = 0; r < 16; r++) {
        u64 o = __shfl_xor_sync(0xFFFFFFFFu, st[r], 1 << LB);
        u64 n = fmul2(cAm, st[r]);
        n = ffma2(cBm, swap2(st[r]), n);
        n = ffma2(cAo, o, n);
        n = ffma2(cBo, swap2(o), n);
        st[r] = n;
    }
}

// ---- gate on a thread/warp bit TB (wires 0..2): smem exchange ----
template<int TB>
__device__ __forceinline__ void gate_warp(u64* st, const u64* g, int t, u64* xbuf) {
#pragma unroll
    for (int r = 0; r < 16; r++) xbuf[r * NT + t] = st[r];
    __syncthreads();
    const int pt  = t ^ (1 << TB);
    const int bit = (t >> TB) & 1;
    u64 cAm = bit ? g[6] : g[0];
    u64 cBm = bit ? g[7] : g[1];
    u64 cAo = bit ? g[4] : g[2];
    u64 cBo = bit ? g[5] : g[3];
#pragma unroll
    for (int r = 0; r < 16; r++) {
        u64 o = xbuf[r * NT + pt];
        u64 n = fmul2(cAm, st[r]);
        n = ffma2(cBm, swap2(st[r]), n);
        n = ffma2(cAo, o, n);
        n = ffma2(cBo, swap2(o), n);
        st[r] = n;
    }
    __syncthreads();
}

// ---- CNOT variants ----
// control = register bit PC, target = register bit PT
template<int PC, int PT>
__device__ __forceinline__ void cnot_reg_rc(u64* st) {
#pragma unroll
    for (int r = 0; r < 16; r++) {
        if (((r >> PC) & 1) == 1 && ((r >> PT) & 1) == 0) {
            u64 tmp = st[r]; st[r] = st[r | (1 << PT)]; st[r | (1 << PT)] = tmp;
        }
    }
}
// control = uniform (thread/lane bit), target = register bit PT
template<int PT>
__device__ __forceinline__ void cnot_reg_uc(u64* st, bool ctrl) {
    if (ctrl) {
#pragma unroll
        for (int r = 0; r < 16; r++) {
            if (((r >> PT) & 1) == 0) {
                u64 tmp = st[r]; st[r] = st[r | (1 << PT)]; st[r | (1 << PT)] = tmp;
            }
        }
    }
}
// control = uniform, target = lane bit LB
template<int LB>
__device__ __forceinline__ void cnot_lane(u64* st, bool ctrl) {
#pragma unroll
    for (int r = 0; r < 16; r++) {
        u64 o = __shfl_xor_sync(0xFFFFFFFFu, st[r], 1 << LB);
        if (ctrl) st[r] = o;
    }
}
// control = uniform, target = thread bit TB
template<int TB>
__device__ __forceinline__ void cnot_warp(u64* st, int t, bool ctrl, u64* xbuf) {
#pragma unroll
    for (int r = 0; r < 16; r++) xbuf[r * NT + t] = st[r];
    __syncthreads();
    const int pt = t ^ (1 << TB);
#pragma unroll
    for (int r = 0; r < 16; r++) {
        u64 o = xbuf[r * NT + pt];
        if (ctrl) st[r] = o;
    }
    __syncthreads();
}
// q=11: control = register bit 0 (wire 11), target = thread bit 7 (wire 0)
__device__ __forceinline__ void cnot_warp_rc(u64* st, int t, u64* xbuf) {
#pragma unroll
    for (int r = 1; r < 16; r += 2) xbuf[(r >> 1) * NT + t] = st[r];
    __syncthreads();
    const int pt = t ^ 128;
#pragma unroll
    for (int r = 1; r < 16; r += 2) st[r] = xbuf[(r >> 1) * NT + pt];
    __syncthreads();
}

// One sweep of 12 single-qubit gates (wires 0..11); gates on distinct wires commute.
__device__ __forceinline__ void apply_sweep(u64* st, const u64* G, int t, int lane, u64* xbuf) {
    gate_reg<3>(st, G + 8 * 8);     // wire 8
    gate_reg<2>(st, G + 9 * 8);     // wire 9
    gate_reg<1>(st, G + 10 * 8);    // wire 10
    gate_reg<0>(st, G + 11 * 8);    // wire 11
    gate_lane<4>(st, G + 3 * 8, lane);  // wire 3
    gate_lane<3>(st, G + 4 * 8, lane);  // wire 4
    gate_lane<2>(st, G + 5 * 8, lane);  // wire 5
    gate_lane<1>(st, G + 6 * 8, lane);  // wire 6
    gate_lane<0>(st, G + 7 * 8, lane);  // wire 7
    gate_warp<7>(st, G + 0 * 8, t, xbuf);  // wire 0
    gate_warp<6>(st, G + 1 * 8, t, xbuf);  // wire 1
    gate_warp<5>(st, G + 2 * 8, t, xbuf);  // wire 2
}

__global__ void __launch_bounds__(NT)
qsim_kernel(const float* __restrict__ x,       // (B, 12)
            const float* __restrict__ w,       // (4, 12, 3)
            const float* __restrict__ ent,     // (4, 12)
            float* __restrict__ out)           // (B, 12)
{
    __shared__ u64   Usm[NGATES * 8];          // 3840 B gate coefficients
    __shared__ u64   xbuf[DIM];                // 32 KB exchange buffer
    __shared__ float red[(NT / 32) * NQ];

    const int b    = blockIdx.x;
    const int t    = threadIdx.x;
    const int lane = t & 31;

    // ---- precompute all 60 gate matrices (one thread per gate) ----
    if (t < NGATES) {
        const float PI = 3.14159265358979323846f;
        float2 u00, u01, u10, u11;
        if (t < NQ) {
            // encoding on wire t: U = RZ(x^2*pi) @ RY(x*pi), per-sample
            float xv = __ldg(&x[b * NQ + t]);
            float s, c;  sincosf(0.5f * PI * xv, &s, &c);
            float sh, ch; sincosf(0.5f * PI * xv * xv, &sh, &ch);
            u00 = make_float2( c * ch, -c * sh);
            u01 = make_float2(-s * ch,  s * sh);
            u10 = make_float2( s * ch,  s * sh);
            u11 = make_float2( c * ch,  c * sh);
        } else {
            // Rot(phi, theta, omega) = RZ(om) @ RY(th) @ RZ(phi), shared
            int gi = t - NQ;   // = l*12 + q
            float phi = __ldg(&w[gi * 3 + 0]);
            float th  = __ldg(&w[gi * 3 + 1]);
            float om  = __ldg(&w[gi * 3 + 2]);
            float s, c;  sincosf(0.5f * th, &s, &c);
            float sp, cp; sincosf(0.5f * (om + phi), &sp, &cp);
            float sm, cm; sincosf(0.5f * (om - phi), &sm, &cm);
            u00 = make_float2( c * cp, -c * sp);
            u01 = make_float2(-s * cm,  s * sm);
            u10 = make_float2( s * cm,  s * sm);
            u11 = make_float2( c * cp,  c * sp);
        }
        u64* g = &Usm[t * 8];
        g[0] = pack2(u00.x, u00.x);  g[1] = pack2(-u00.y, u00.y);
        g[2] = pack2(u01.x, u01.x);  g[3] = pack2(-u01.y, u01.y);
        g[4] = pack2(u10.x, u10.x);  g[5] = pack2(-u10.y, u10.y);
        g[6] = pack2(u11.x, u11.x);  g[7] = pack2(-u11.y, u11.y);
    }
    __syncthreads();

    // ---- register-resident state: amplitude of index (t<<4)|r in st[r] ----
    u64 st[16];
#pragma unroll
    for (int r = 0; r < 16; r++) st[r] = 0ULL;
    if (t == 0) st[0] = pack2(1.0f, 0.0f);

    // encoding sweep
    apply_sweep(st, Usm, t, lane, xbuf);

    // variational layers
    for (int l = 0; l < NLAYERS; l++) {
        apply_sweep(st, &Usm[(NQ + l * NQ) * 8], t, lane, xbuf);
        const float* el = &ent[l * NQ];
        // CNOT ring q -> q+1 (order matters; masks are CTA-uniform)
        if (__ldg(&el[0])  > 0.5f) cnot_warp<6>(st, t, (t >> 7) & 1, xbuf);  // c=w0,t=w1
        if (__ldg(&el[1])  > 0.5f) cnot_warp<5>(st, t, (t >> 6) & 1, xbuf);  // c=w1,t=w2
        if (__ldg(&el[2])  > 0.5f) cnot_lane<4>(st, (t >> 5) & 1);           // c=w2,t=w3
        if (__ldg(&el[3])  > 0.5f) cnot_lane<3>(st, (lane >> 4) & 1);        // c=w3,t=w4
        if (__ldg(&el[4])  > 0.5f) cnot_lane<2>(st, (lane >> 3) & 1);        // c=w4,t=w5
        if (__ldg(&el[5])  > 0.5f) cnot_lane<1>(st, (lane >> 2) & 1);        // c=w5,t=w6
        if (__ldg(&el[6])  > 0.5f) cnot_lane<0>(st, (lane >> 1) & 1);        // c=w6,t=w7
        if (__ldg(&el[7])  > 0.5f) cnot_reg_uc<3>(st, lane & 1);             // c=w7,t=w8
        if (__ldg(&el[8])  > 0.5f) cnot_reg_rc<3, 2>(st);                    // c=w8,t=w9
        if (__ldg(&el[9])  > 0.5f) cnot_reg_rc<2, 1>(st);                    // c=w9,t=w10
        if (__ldg(&el[10]) > 0.5f) cnot_reg_rc<1, 0>(st);                    // c=w10,t=w11
        if (__ldg(&el[11]) > 0.5f) cnot_warp_rc(st, t, xbuf);                // c=w11,t=w0
    }

    // ---- readout: <Z_q> ----
    float psum = 0.f, a8 = 0.f, a9 = 0.f, a10 = 0.f, a11 = 0.f;
#pragma unroll
    for (int r = 0; r < 16; r++) {
        float re, im; unpack2(st[r], re, im);
        float p = re * re + im * im;
        psum += p;
        a8  += ((r >> 3) & 1) ? -p : p;   // wire 8  (state bit 3)
        a9  += ((r >> 2) & 1) ? -p : p;   // wire 9
        a10 += ((r >> 1) & 1) ? -p : p;   // wire 10
        a11 += ( r       & 1) ? -p : p;   // wire 11
    }
    float acc[NQ];
#pragma unroll
    for (int q = 0; q < 8; q++)           // wires 0..7: sign from thread bit (7-q)
        acc[q] = ((t >> (7 - q)) & 1) ? -psum : psum;
    acc[8] = a8; acc[9] = a9; acc[10] = a10; acc[11] = a11;

    const int wid = t >> 5;
#pragma unroll
    for (int q = 0; q < NQ; q++) {
        float v = acc[q];
#pragma unroll
        for (int o = 16; o; o >>= 1) v += __shfl_xor_sync(0xFFFFFFFFu, v, o);
        if (lane == 0) red[wid * NQ + q] = v;
    }
    __syncthreads();

    if (t < NQ) {
        float s = 0.f;
#pragma unroll
        for (int wi = 0; wi < NT / 32; wi++) s += red[wi * NQ + t];
        out[b * NQ + t] = s;   // SCALE = 1
    }
}

extern "C" void kernel_launch(void* const* d_in, const int* in_sizes, int n_in,
                              void* d_out, int out_size)
{
    const float* x   = (const float*)d_in[0];   // (B, 12)
    const float* w   = (const float*)d_in[1];   // (4, 12, 3)
    const float* ent = (const float*)d_in[2];   // (4, 12)
    float* out = (float*)d_out;                 // (B, 12)

    int B = in_sizes[0] / NQ;
    qsim_kernel<<<B, NT>>>(x, w, ent, out);
}